// round 1
// baseline (speedup 1.0000x reference)
#include <cuda_runtime.h>
#include <cstdint>

#define BQ     32
#define NKEYS  4096
#define DIM    64
#define NQ     8
#define CPB    4          // chunks per batch -> grid 128
#define CHUNK  1024
#define TILE   128
#define NTILES 8
#define KPAD   68         // padded row stride (floats) for keys/values tiles

// ---- scratch (no allocations allowed) ----
__device__ float g_pv[BQ * CPB * NQ * DIM];   // partial PV sums
__device__ float g_cs[BQ * CPB * NQ];         // partial column sums

// ---- cp.async helpers ----
__device__ __forceinline__ void cp16(uint32_t s, const float* g) {
    asm volatile("cp.async.cg.shared.global [%0], [%1], 16;\n" :: "r"(s), "l"(g));
}
__device__ __forceinline__ void cp_commit() {
    asm volatile("cp.async.commit_group;\n" ::: "memory");
}
template <int N>
__device__ __forceinline__ void cp_wait() {
    asm volatile("cp.async.wait_group %0;\n" :: "n"(N) : "memory");
}

// ---- smem layout (float offsets) ----
#define OFF_Q   0
#define Q_SZ    (NQ * KPAD)                 // 544
#define OFF_K   (OFF_Q + Q_SZ)              // 544
#define KS_SZ   (TILE * KPAD)               // 8704
#define OFF_V   (OFF_K + 2 * KS_SZ)         // 17952
#define OFF_P   (OFF_V + 2 * KS_SZ)         // 35360
#define OFF_PV  (OFF_P + TILE * NQ)         // 36384
#define OFF_WS  (OFF_PV + 2048)             // 38432
#define SMEM_FLOATS (OFF_WS + 64)           // 38496 -> 153,984 bytes

extern __shared__ float smem[];

__global__ __launch_bounds__(256, 1)
void attn_partial(const float* __restrict__ keys,
                  const float* __restrict__ vals,
                  const float* __restrict__ query) {
    const int tid   = threadIdx.x;
    const int b     = blockIdx.x >> 2;
    const int chunk = blockIdx.x & 3;
    const int n0    = chunk * CHUNK;
    const uint32_t sbase = (uint32_t)__cvta_generic_to_shared(smem);

    const float* kg0 = keys + ((size_t)b * NKEYS + n0) * DIM;
    const float* vg0 = vals + ((size_t)b * NKEYS + n0) * DIM;

    // ---- prefetch tile 0 ----
    {
#pragma unroll
        for (int i = 0; i < 8; ++i) {
            int c = tid + i * 256;              // 0..2047
            int r = c >> 4, s = (c & 15) << 2;  // row, float offset
            cp16(sbase + (uint32_t)((OFF_K + r * KPAD + s) << 2), kg0 + r * DIM + s);
            cp16(sbase + (uint32_t)((OFF_V + r * KPAD + s) << 2), vg0 + r * DIM + s);
        }
        cp_commit();
    }

    // ---- load query (8 x 64) ----
    if (tid < 128) {
        int r = tid >> 4, s = (tid & 15) << 2;
        *(float4*)&smem[OFF_Q + r * KPAD + s] =
            *(const float4*)(query + ((size_t)b * NQ + r) * DIM + s);
    }

    const int lane = tid & 31;
    const int warp = tid >> 5;
    const int k_qk = tid >> 1;          // QK: key index within tile
    const int m0   = (tid & 1) * 4;     // QK: query group (0 or 4)
    const int m0p  = (warp & 1) * 4;    // PV: query group per warp
    const int kq   = warp >> 1;         // PV: key quarter per warp

    float cs0 = 0.f, cs1 = 0.f, cs2 = 0.f, cs3 = 0.f;
    float pv00 = 0.f, pv01 = 0.f, pv10 = 0.f, pv11 = 0.f;
    float pv20 = 0.f, pv21 = 0.f, pv30 = 0.f, pv31 = 0.f;

    for (int t = 0; t < NTILES; ++t) {
        const int buf = t & 1;
        if (t + 1 < NTILES) {
            const int nb = (t + 1) & 1;
            const float* kg = kg0 + (size_t)(t + 1) * TILE * DIM;
            const float* vg = vg0 + (size_t)(t + 1) * TILE * DIM;
#pragma unroll
            for (int i = 0; i < 8; ++i) {
                int c = tid + i * 256;
                int r = c >> 4, s = (c & 15) << 2;
                cp16(sbase + (uint32_t)((OFF_K + nb * KS_SZ + r * KPAD + s) << 2), kg + r * DIM + s);
                cp16(sbase + (uint32_t)((OFF_V + nb * KS_SZ + r * KPAD + s) << 2), vg + r * DIM + s);
            }
            cp_commit();
            cp_wait<1>();
        } else {
            cp_wait<0>();
        }
        __syncthreads();

        // ---------- QK + per-key softmax over the 8 queries ----------
        {
            const float* kb = &smem[OFF_K + buf * KS_SZ + k_qk * KPAD];
            float a0 = 0.f, a1 = 0.f, a2 = 0.f, a3 = 0.f;
#pragma unroll
            for (int d4 = 0; d4 < 16; ++d4) {
                float4 kv = *(const float4*)(kb + (d4 << 2));
                float4 q0 = *(const float4*)&smem[OFF_Q + (m0 + 0) * KPAD + (d4 << 2)];
                float4 q1 = *(const float4*)&smem[OFF_Q + (m0 + 1) * KPAD + (d4 << 2)];
                float4 q2 = *(const float4*)&smem[OFF_Q + (m0 + 2) * KPAD + (d4 << 2)];
                float4 q3 = *(const float4*)&smem[OFF_Q + (m0 + 3) * KPAD + (d4 << 2)];
                a0 += kv.x * q0.x + kv.y * q0.y + kv.z * q0.z + kv.w * q0.w;
                a1 += kv.x * q1.x + kv.y * q1.y + kv.z * q1.z + kv.w * q1.w;
                a2 += kv.x * q2.x + kv.y * q2.y + kv.z * q2.z + kv.w * q2.w;
                a3 += kv.x * q3.x + kv.y * q3.y + kv.z * q3.z + kv.w * q3.w;
            }
            a0 *= 0.125f; a1 *= 0.125f; a2 *= 0.125f; a3 *= 0.125f;

            float mx = fmaxf(fmaxf(a0, a1), fmaxf(a2, a3));
            mx = fmaxf(mx, __shfl_xor_sync(0xffffffffu, mx, 1));
            float e0 = __expf(a0 - mx), e1 = __expf(a1 - mx);
            float e2 = __expf(a2 - mx), e3 = __expf(a3 - mx);
            float sum = e0 + e1 + e2 + e3;
            sum += __shfl_xor_sync(0xffffffffu, sum, 1);
            float inv = 1.0f / sum;
            float p0 = e0 * inv + 1e-8f;
            float p1 = e1 * inv + 1e-8f;
            float p2 = e2 * inv + 1e-8f;
            float p3 = e3 * inv + 1e-8f;
            *(float4*)&smem[OFF_P + k_qk * NQ + m0] = make_float4(p0, p1, p2, p3);
            cs0 += p0; cs1 += p1; cs2 += p2; cs3 += p3;
        }
        __syncthreads();

        // ---------- PV accumulate (rank-1 updates in registers) ----------
        {
            const float* vb = &smem[OFF_V + buf * KS_SZ];
#pragma unroll 8
            for (int kk = 0; kk < 32; ++kk) {
                int k = kq * 32 + kk;
                float4 pk = *(const float4*)&smem[OFF_P + k * NQ + m0p];  // warp-uniform -> broadcast
                float2 vv = *(const float2*)(vb + k * KPAD + (lane << 1));
                pv00 += pk.x * vv.x; pv01 += pk.x * vv.y;
                pv10 += pk.y * vv.x; pv11 += pk.y * vv.y;
                pv20 += pk.z * vv.x; pv21 += pk.z * vv.y;
                pv30 += pk.w * vv.x; pv31 += pk.w * vv.y;
            }
        }
        __syncthreads();
    }

    // ---------- colsum reduce (lanes of same parity share the m-group) ----------
#pragma unroll
    for (int off = 16; off >= 2; off >>= 1) {
        cs0 += __shfl_xor_sync(0xffffffffu, cs0, off);
        cs1 += __shfl_xor_sync(0xffffffffu, cs1, off);
        cs2 += __shfl_xor_sync(0xffffffffu, cs2, off);
        cs3 += __shfl_xor_sync(0xffffffffu, cs3, off);
    }
    if (lane < 2) {
        smem[OFF_WS + warp * 8 + lane * 4 + 0] = cs0;
        smem[OFF_WS + warp * 8 + lane * 4 + 1] = cs1;
        smem[OFF_WS + warp * 8 + lane * 4 + 2] = cs2;
        smem[OFF_WS + warp * 8 + lane * 4 + 3] = cs3;
    }
    // ---------- PV partials to smem ----------
    {
        int l2 = lane << 1;
        smem[OFF_PV + (warp * 4 + 0) * 64 + l2]     = pv00;
        smem[OFF_PV + (warp * 4 + 0) * 64 + l2 + 1] = pv01;
        smem[OFF_PV + (warp * 4 + 1) * 64 + l2]     = pv10;
        smem[OFF_PV + (warp * 4 + 1) * 64 + l2 + 1] = pv11;
        smem[OFF_PV + (warp * 4 + 2) * 64 + l2]     = pv20;
        smem[OFF_PV + (warp * 4 + 2) * 64 + l2 + 1] = pv21;
        smem[OFF_PV + (warp * 4 + 3) * 64 + l2]     = pv30;
        smem[OFF_PV + (warp * 4 + 3) * 64 + l2 + 1] = pv31;
    }
    __syncthreads();

    if (tid < 8) {
        float s = 0.f;
#pragma unroll
        for (int w = 0; w < 8; ++w) s += smem[OFF_WS + w * 8 + tid];
        g_cs[(b * CPB + chunk) * NQ + tid] = s;
    }
    {
        int m = tid >> 5, v = tid & 31;
        int mg = m >> 2, j = m & 3;
        float s1 = 0.f, s2 = 0.f;
#pragma unroll
        for (int q = 0; q < 4; ++q) {
            int w = q * 2 + mg;
            s1 += smem[OFF_PV + (w * 4 + j) * 64 + v];
            s2 += smem[OFF_PV + (w * 4 + j) * 64 + v + 32];
        }
        float* dst = &g_pv[((size_t)(b * CPB + chunk) * NQ + m) * DIM];
        dst[v]      = s1;
        dst[v + 32] = s2;
    }
}

__global__ void attn_finalize(float* __restrict__ out) {
    const int b = blockIdx.x;
    const int m = threadIdx.x >> 6;
    const int v = threadIdx.x & 63;
    float cs = 0.f, pv = 0.f;
#pragma unroll
    for (int c = 0; c < CPB; ++c) {
        cs += g_cs[(b * CPB + c) * NQ + m];
        pv += g_pv[((size_t)(b * CPB + c) * NQ + m) * DIM + v];
    }
    out[((size_t)b * NQ + m) * DIM + v] = pv / cs;
}

extern "C" void kernel_launch(void* const* d_in, const int* in_sizes, int n_in,
                              void* d_out, int out_size) {
    const float* keys  = (const float*)d_in[0];
    const float* vals  = (const float*)d_in[1];
    const float* query = (const float*)d_in[2];
    float* out = (float*)d_out;

    cudaFuncSetAttribute(attn_partial,
                         cudaFuncAttributeMaxDynamicSharedMemorySize,
                         SMEM_FLOATS * sizeof(float));
    attn_partial<<<BQ * CPB, 256, SMEM_FLOATS * sizeof(float)>>>(keys, vals, query);
    attn_finalize<<<BQ, 512>>>(out);
}